// round 1
// baseline (speedup 1.0000x reference)
#include <cuda_runtime.h>
#include <cuda_bf16.h>
#include <math.h>

// Problem shape (fixed by the dataset): N=8, C=128, H=W=32 -> HW=1024.
#define NB   8
#define CC   128
#define HW   1024
#define BM   128
#define BN   128
#define BK   16

// Scratch accumulators (allocation-free rule: __device__ globals).
__device__ float g_rnorm[NB * HW];
__device__ float g_inorm[NB * HW];
__device__ float g_rowL [NB * HW];   // sum_q logit            (per p)
__device__ float g_rowLM[NB * HW];   // sum_q logit*mask       (per p)
__device__ float g_colL [NB * HW];   // sum_p logit            (per q)
__device__ float g_colLM[NB * HW];   // sum_p logit*mask       (per q)

// ---------------------------------------------------------------------------
// prep: squared norms per pixel vector + zero the accumulators
// ---------------------------------------------------------------------------
__global__ void prep_kernel(const float* __restrict__ R, const float* __restrict__ I)
{
    int idx = blockIdx.x * blockDim.x + threadIdx.x;   // 0 .. NB*HW-1
    if (idx >= NB * HW) return;
    int n = idx >> 10;
    int p = idx & (HW - 1);
    const float* a = R + n * CC * HW + p;
    const float* b = I + n * CC * HW + p;
    float sa = 0.f, sb = 0.f;
    #pragma unroll 8
    for (int c = 0; c < CC; c++) {
        float va = a[c * HW];
        float vb = b[c * HW];
        sa = fmaf(va, va, sa);
        sb = fmaf(vb, vb, sb);
    }
    g_rnorm[idx] = sa;
    g_inorm[idx] = sb;
    g_rowL[idx]  = 0.f;
    g_rowLM[idx] = 0.f;
    g_colL[idx]  = 0.f;
    g_colLM[idx] = 0.f;
}

// ---------------------------------------------------------------------------
// main fused tile kernel: 128x128 tile of the (p,q) plane per CTA.
// dot[p][q] = sum_c R[n,c,p] * I[n,c,q]   (both operands k-major, unit-stride
// along p / q -> perfectly coalesced tile loads).
// ---------------------------------------------------------------------------
__global__ __launch_bounds__(256, 2)
void tile_kernel(const float* __restrict__ R, const float* __restrict__ I,
                 const int* __restrict__ RM, const int* __restrict__ IM)
{
    __shared__ float As[BK][BM];
    __shared__ float Bs[BK][BN];
    __shared__ float cbuf[16][BN];

    const int n  = blockIdx.z;
    const int p0 = blockIdx.y * BM;
    const int q0 = blockIdx.x * BN;
    const int tid = threadIdx.x;
    const int tx = tid & 15;        // q direction (8 cols each)
    const int ty = tid >> 4;        // p direction (8 rows each)

    const float* Rb = R + n * CC * HW;
    const float* Ib = I + n * CC * HW;

    float dot[8][8];
    #pragma unroll
    for (int i = 0; i < 8; i++)
        #pragma unroll
        for (int j = 0; j < 8; j++)
            dot[i][j] = 0.f;

    for (int k0 = 0; k0 < CC; k0 += BK) {
        // Stage 16 (c) x 128 (pixel) fp32 per operand: 512 float4 each,
        // 2 float4 per thread per operand, fully coalesced.
        #pragma unroll
        for (int l = 0; l < 2; l++) {
            int f   = tid + l * 256;      // float4 index 0..511
            int row = f >> 5;             // 32 float4 per row
            int c4  = (f & 31) * 4;
            float4 va = *reinterpret_cast<const float4*>(Rb + (k0 + row) * HW + p0 + c4);
            *reinterpret_cast<float4*>(&As[row][c4]) = va;
            float4 vb = *reinterpret_cast<const float4*>(Ib + (k0 + row) * HW + q0 + c4);
            *reinterpret_cast<float4*>(&Bs[row][c4]) = vb;
        }
        __syncthreads();

        #pragma unroll
        for (int k = 0; k < BK; k++) {
            float a[8], b[8];
            *reinterpret_cast<float4*>(a)     = *reinterpret_cast<float4*>(&As[k][ty * 8]);
            *reinterpret_cast<float4*>(a + 4) = *reinterpret_cast<float4*>(&As[k][ty * 8 + 4]);
            *reinterpret_cast<float4*>(b)     = *reinterpret_cast<float4*>(&Bs[k][tx * 8]);
            *reinterpret_cast<float4*>(b + 4) = *reinterpret_cast<float4*>(&Bs[k][tx * 8 + 4]);
            #pragma unroll
            for (int i = 0; i < 8; i++)
                #pragma unroll
                for (int j = 0; j < 8; j++)
                    dot[i][j] = fmaf(a[i], b[j], dot[i][j]);
        }
        __syncthreads();
    }

    // --------------------------- fused epilogue ---------------------------
    float rn[8], inq[8];
    int   rmv[8], imv[8];
    #pragma unroll
    for (int i = 0; i < 8; i++) {
        rn[i]  = g_rnorm[n * HW + p0 + ty * 8 + i];
        rmv[i] = RM[n * HW + p0 + ty * 8 + i];
    }
    #pragma unroll
    for (int j = 0; j < 8; j++) {
        inq[j] = g_inorm[n * HW + q0 + tx * 8 + j];
        imv[j] = IM[n * HW + q0 + tx * 8 + j];
    }

    float rowL[8], rowLM[8], colL[8], colLM[8];
    #pragma unroll
    for (int i = 0; i < 8; i++) { rowL[i] = 0.f; rowLM[i] = 0.f; }
    #pragma unroll
    for (int j = 0; j < 8; j++) { colL[j] = 0.f; colLM[j] = 0.f; }

    #pragma unroll
    for (int i = 0; i < 8; i++) {
        #pragma unroll
        for (int j = 0; j < 8; j++) {
            float dist  = rn[i] + inq[j] - 2.0f * dot[i][j];
            float e1    = expf(-dist);
            float logit = expf(e1 / 10.0f);
            rowL[i] += logit;
            colL[j] += logit;
            if (rmv[i] == imv[j]) {
                rowLM[i] += logit;
                colLM[j] += logit;
            }
        }
    }

    // Row reduction: reduce across tx (16 lanes inside each half-warp).
    #pragma unroll
    for (int i = 0; i < 8; i++) {
        float a = rowL[i], bm = rowLM[i];
        #pragma unroll
        for (int off = 1; off < 16; off <<= 1) {
            a  += __shfl_xor_sync(0xffffffffu, a,  off);
            bm += __shfl_xor_sync(0xffffffffu, bm, off);
        }
        if (tx == 0) {
            atomicAdd(&g_rowL [n * HW + p0 + ty * 8 + i], a);
            atomicAdd(&g_rowLM[n * HW + p0 + ty * 8 + i], bm);
        }
    }

    // Column reduction: transpose-reduce through shared memory.
    __syncthreads();
    #pragma unroll
    for (int j = 0; j < 8; j++) cbuf[ty][tx * 8 + j] = colL[j];
    __syncthreads();
    if (tid < BN) {
        float s = 0.f;
        #pragma unroll
        for (int y = 0; y < 16; y++) s += cbuf[y][tid];
        atomicAdd(&g_colL[n * HW + q0 + tid], s);
    }
    __syncthreads();
    #pragma unroll
    for (int j = 0; j < 8; j++) cbuf[ty][tx * 8 + j] = colLM[j];
    __syncthreads();
    if (tid < BN) {
        float s = 0.f;
        #pragma unroll
        for (int y = 0; y < 16; y++) s += cbuf[y][tid];
        atomicAdd(&g_colLM[n * HW + q0 + tid], s);
    }
}

// ---------------------------------------------------------------------------
// finalize: masked -log mean over the 2*N*HW loss vector -> scalar
// ---------------------------------------------------------------------------
__global__ void finalize_kernel(const int* __restrict__ RM, const int* __restrict__ IM,
                                float* __restrict__ out)
{
    __shared__ double s_t[256];
    __shared__ float  s_c[256];
    int tid = threadIdx.x;
    double tot = 0.0;
    float  cnt = 0.f;
    for (int j = tid; j < NB * HW; j += 256) {
        // row side (fg from rgb mask)
        {
            float l  = g_rowL[j] + 1e-6f;
            float lm = g_rowLM[j];
            float v  = lm / l;
            if (RM[j] > 0 && v != 0.0f) { tot -= (double)logf(v); cnt += 1.f; }
        }
        // col side (fg from ir mask)
        {
            float l  = g_colL[j] + 1e-6f;
            float lm = g_colLM[j];
            float v  = lm / l;
            if (IM[j] > 0 && v != 0.0f) { tot -= (double)logf(v); cnt += 1.f; }
        }
    }
    s_t[tid] = tot;
    s_c[tid] = cnt;
    __syncthreads();
    for (int s = 128; s > 0; s >>= 1) {
        if (tid < s) { s_t[tid] += s_t[tid + s]; s_c[tid] += s_c[tid + s]; }
        __syncthreads();
    }
    if (tid == 0) out[0] = (float)(s_t[0] / (double)s_c[0]);
}

// ---------------------------------------------------------------------------
extern "C" void kernel_launch(void* const* d_in, const int* in_sizes, int n_in,
                              void* d_out, int out_size)
{
    const float* R  = (const float*)d_in[0];   // rgb_map  (N,C,H,W) fp32
    const float* I  = (const float*)d_in[1];   // ir_map   (N,C,H,W) fp32
    const int*   RM = (const int*)  d_in[2];   // rgb_mask (N,H,W)   int32
    const int*   IM = (const int*)  d_in[3];   // ir_mask  (N,H,W)   int32
    float* out = (float*)d_out;

    prep_kernel<<<(NB * HW + 255) / 256, 256>>>(R, I);

    dim3 grid(HW / BN, HW / BM, NB);           // (8, 8, 8) = 512 CTAs
    tile_kernel<<<grid, 256>>>(R, I, RM, IM);

    finalize_kernel<<<1, 256>>>(RM, IM, out);
}

// round 3
// speedup vs baseline: 4.1965x; 4.1965x over previous
#include <cuda_runtime.h>
#include <cuda_bf16.h>
#include <math.h>
#include <stdint.h>

// Problem shape (fixed): N=8, C=128, H=W=32 -> HW=1024.
#define NB   8
#define CC   128
#define HW   1024
#define BM   128
#define BN   128
#define BK   64          // k-chunk staged in smem (2 chunks of 64 = CC)

// ---------------------------------------------------------------------------
// Device scratch (allocation-free rule: __device__ globals)
// ---------------------------------------------------------------------------
__device__ __nv_bfloat16 g_Rbf[NB * CC * HW];
__device__ __nv_bfloat16 g_Ibf[NB * CC * HW];
__device__ float g_rnorm[NB * HW];
__device__ float g_inorm[NB * HW];
__device__ float g_rowL [NB * HW];
__device__ float g_rowLM[NB * HW];
__device__ float g_colL [NB * HW];
__device__ float g_colLM[NB * HW];
__device__ float g_tot;
__device__ float g_cnt;

// ---------------------------------------------------------------------------
// PTX helpers
// ---------------------------------------------------------------------------
__device__ __forceinline__ uint32_t smem_u32(const void* p) {
    return (uint32_t)__cvta_generic_to_shared(p);
}

__device__ __forceinline__ void ldsm_x4_t(uint32_t& r0, uint32_t& r1,
                                          uint32_t& r2, uint32_t& r3, uint32_t addr) {
    asm volatile("ldmatrix.sync.aligned.m8n8.x4.trans.shared.b16 {%0,%1,%2,%3}, [%4];"
                 : "=r"(r0), "=r"(r1), "=r"(r2), "=r"(r3) : "r"(addr));
}

__device__ __forceinline__ void ldsm_x2_t(uint32_t& r0, uint32_t& r1, uint32_t addr) {
    asm volatile("ldmatrix.sync.aligned.m8n8.x2.trans.shared.b16 {%0,%1}, [%2];"
                 : "=r"(r0), "=r"(r1) : "r"(addr));
}

__device__ __forceinline__ void mma_bf16(float& d0, float& d1, float& d2, float& d3,
                                         uint32_t a0, uint32_t a1, uint32_t a2, uint32_t a3,
                                         uint32_t b0, uint32_t b1) {
    asm volatile("mma.sync.aligned.m16n8k16.row.col.f32.bf16.bf16.f32 "
                 "{%0,%1,%2,%3}, {%4,%5,%6,%7}, {%8,%9}, {%0,%1,%2,%3};"
                 : "+f"(d0), "+f"(d1), "+f"(d2), "+f"(d3)
                 : "r"(a0), "r"(a1), "r"(a2), "r"(a3), "r"(b0), "r"(b1));
}

// ---------------------------------------------------------------------------
// zero accumulators
// ---------------------------------------------------------------------------
__global__ void zero_kernel() {
    int idx = blockIdx.x * blockDim.x + threadIdx.x;
    if (idx < NB * HW) {
        g_rnorm[idx] = 0.f; g_inorm[idx] = 0.f;
        g_rowL[idx] = 0.f;  g_rowLM[idx] = 0.f;
        g_colL[idx] = 0.f;  g_colLM[idx] = 0.f;
    }
    if (idx == 0) { g_tot = 0.f; g_cnt = 0.f; }
}

// ---------------------------------------------------------------------------
// prep: squared norms (4-way channel split, atomic partials) + fp32->bf16
// grid: 128 blocks x 256 threads. block b: channel quarter = b>>5,
// pixels (b&31)*256 .. +255
// ---------------------------------------------------------------------------
__global__ void prep_kernel(const float* __restrict__ R, const float* __restrict__ I)
{
    int b  = blockIdx.x;
    int cq = b >> 5;                        // 0..3
    int pg = ((b & 31) << 8) + threadIdx.x; // global pixel 0..8191
    int n  = pg >> 10;
    int p  = pg & (HW - 1);

    const float* a  = R + n * CC * HW + cq * 32 * HW + p;
    const float* bb = I + n * CC * HW + cq * 32 * HW + p;
    __nv_bfloat16* oa = g_Rbf + n * CC * HW + cq * 32 * HW + p;
    __nv_bfloat16* ob = g_Ibf + n * CC * HW + cq * 32 * HW + p;

    float sa = 0.f, sb = 0.f;
    #pragma unroll 8
    for (int c = 0; c < 32; c++) {
        float va = a[c * HW];
        float vb = bb[c * HW];
        oa[c * HW] = __float2bfloat16(va);
        ob[c * HW] = __float2bfloat16(vb);
        sa = fmaf(va, va, sa);
        sb = fmaf(vb, vb, sb);
    }
    atomicAdd(&g_rnorm[pg], sa);
    atomicAdd(&g_inorm[pg], sb);
}

// ---------------------------------------------------------------------------
// fused bf16 tensor-core tile kernel: 128x128 (p,q) tile per CTA.
// dot[p][q] = sum_c R[n,c,p] * I[n,c,q]. Operands are k-major in gmem
// (unit stride along p/q) -> coalesced staging; ldmatrix.trans yields
// row-major A / col-major B fragments for mma.m16n8k16.
// ---------------------------------------------------------------------------
__global__ __launch_bounds__(256, 2)
void tile_kernel(const int* __restrict__ RM, const int* __restrict__ IM)
{
    __shared__ __nv_bfloat16 As[BK][BM + 8];   // +8 pad: 272B rows, conflict-free ldmatrix
    __shared__ __nv_bfloat16 Bs[BK][BN + 8];

    const int n  = blockIdx.z;
    const int p0 = blockIdx.y * BM;
    const int q0 = blockIdx.x * BN;
    const int tid  = threadIdx.x;
    const int wid  = tid >> 5;
    const int lane = tid & 31;
    const int warp_m = wid >> 2;   // 0..1  (64 rows each)
    const int warp_n = wid & 3;    // 0..3  (32 cols each)

    const __nv_bfloat16* Rb = g_Rbf + n * CC * HW;
    const __nv_bfloat16* Ib = g_Ibf + n * CC * HW;

    float acc[4][4][4];
    #pragma unroll
    for (int mi = 0; mi < 4; mi++)
        #pragma unroll
        for (int ni = 0; ni < 4; ni++)
            #pragma unroll
            for (int r = 0; r < 4; r++)
                acc[mi][ni][r] = 0.f;

    // ldmatrix lane decomposition (constant per thread)
    const int sub   = lane >> 3;    // 0..3 sub-matrix for x4
    const int lrow  = lane & 7;
    const int a_kad = lrow + ((sub >> 1) ? 8 : 0);
    const int a_mad = warp_m * 64 + ((sub & 1) ? 8 : 0);
    const int b_kad = lrow + (((lane >> 3) & 1) ? 8 : 0);

    for (int kk = 0; kk < CC; kk += BK) {
        // Stage BK x 128 bf16 per operand: 64 rows x 16 uint4 = 1024 uint4
        // each, 4 per thread per operand, fully coalesced.
        #pragma unroll
        for (int l = 0; l < 4; l++) {
            int f   = tid + l * 256;   // uint4 index 0..1023
            int row = f >> 4;          // 16 uint4 per 128-elem row
            int c8  = (f & 15) * 8;
            uint4 va = *reinterpret_cast<const uint4*>(Rb + (kk + row) * HW + p0 + c8);
            *reinterpret_cast<uint4*>(&As[row][c8]) = va;
            uint4 vb = *reinterpret_cast<const uint4*>(Ib + (kk + row) * HW + q0 + c8);
            *reinterpret_cast<uint4*>(&Bs[row][c8]) = vb;
        }
        __syncthreads();

        #pragma unroll
        for (int ks = 0; ks < BK / 16; ks++) {
            const int k0 = ks * 16;
            uint32_t afr[4][4];
            #pragma unroll
            for (int mi = 0; mi < 4; mi++) {
                uint32_t addr = smem_u32(&As[k0 + a_kad][a_mad + mi * 16]);
                ldsm_x4_t(afr[mi][0], afr[mi][1], afr[mi][2], afr[mi][3], addr);
            }
            uint32_t bfr[4][2];
            #pragma unroll
            for (int ni = 0; ni < 4; ni++) {
                uint32_t addr = smem_u32(&Bs[k0 + b_kad][warp_n * 32 + ni * 8]);
                ldsm_x2_t(bfr[ni][0], bfr[ni][1], addr);
            }
            #pragma unroll
            for (int mi = 0; mi < 4; mi++)
                #pragma unroll
                for (int ni = 0; ni < 4; ni++)
                    mma_bf16(acc[mi][ni][0], acc[mi][ni][1], acc[mi][ni][2], acc[mi][ni][3],
                             afr[mi][0], afr[mi][1], afr[mi][2], afr[mi][3],
                             bfr[ni][0], bfr[ni][1]);
        }
        __syncthreads();
    }

    // --------------------------- fused epilogue ---------------------------
    const int g  = lane >> 2;   // group row 0..7
    const int tg = lane & 3;    // col pair 0..3
    const int base = n * HW;

    float rn2[4][2]; int rm2[4][2];
    #pragma unroll
    for (int mi = 0; mi < 4; mi++) {
        int r = p0 + warp_m * 64 + mi * 16 + g;
        rn2[mi][0] = g_rnorm[base + r];     rm2[mi][0] = RM[base + r];
        rn2[mi][1] = g_rnorm[base + r + 8]; rm2[mi][1] = RM[base + r + 8];
    }
    float in2[4][2]; int im2[4][2];
    #pragma unroll
    for (int ni = 0; ni < 4; ni++) {
        int c = q0 + warp_n * 32 + ni * 8 + tg * 2;
        in2[ni][0] = g_inorm[base + c];     im2[ni][0] = IM[base + c];
        in2[ni][1] = g_inorm[base + c + 1]; im2[ni][1] = IM[base + c + 1];
    }

    float rowS[4][2], rowM[4][2], colS[4][2], colM[4][2];
    #pragma unroll
    for (int i = 0; i < 4; i++)
        #pragma unroll
        for (int j = 0; j < 2; j++) {
            rowS[i][j] = 0.f; rowM[i][j] = 0.f;
            colS[i][j] = 0.f; colM[i][j] = 0.f;
        }

    #pragma unroll
    for (int mi = 0; mi < 4; mi++)
        #pragma unroll
        for (int ni = 0; ni < 4; ni++)
            #pragma unroll
            for (int r = 0; r < 4; r++) {
                int ri = r >> 1;   // 0: rows g, 1: rows g+8
                int ci = r & 1;    // col pair element
                float dist  = rn2[mi][ri] + in2[ni][ci] - 2.0f * acc[mi][ni][r];
                float logit = __expf(__expf(-dist) * 0.1f);
                rowS[mi][ri] += logit;
                colS[ni][ci] += logit;
                if (rm2[mi][ri] == im2[ni][ci]) {
                    rowM[mi][ri] += logit;
                    colM[ni][ci] += logit;
                }
            }

    // Row reduce across tg (cols): xor 1, 2. tg==0 lanes commit.
    #pragma unroll
    for (int mi = 0; mi < 4; mi++)
        #pragma unroll
        for (int ri = 0; ri < 2; ri++) {
            float v = rowS[mi][ri], m = rowM[mi][ri];
            v += __shfl_xor_sync(0xffffffffu, v, 1);
            v += __shfl_xor_sync(0xffffffffu, v, 2);
            m += __shfl_xor_sync(0xffffffffu, m, 1);
            m += __shfl_xor_sync(0xffffffffu, m, 2);
            if (tg == 0) {
                int r = p0 + warp_m * 64 + mi * 16 + g + ri * 8;
                atomicAdd(&g_rowL [base + r], v);
                atomicAdd(&g_rowLM[base + r], m);
            }
        }

    // Col reduce across g (rows): xor 4, 8, 16. g==0 lanes commit.
    #pragma unroll
    for (int ni = 0; ni < 4; ni++)
        #pragma unroll
        for (int ci = 0; ci < 2; ci++) {
            float v = colS[ni][ci], m = colM[ni][ci];
            v += __shfl_xor_sync(0xffffffffu, v, 4);
            v += __shfl_xor_sync(0xffffffffu, v, 8);
            v += __shfl_xor_sync(0xffffffffu, v, 16);
            m += __shfl_xor_sync(0xffffffffu, m, 4);
            m += __shfl_xor_sync(0xffffffffu, m, 8);
            m += __shfl_xor_sync(0xffffffffu, m, 16);
            if (g == 0) {
                int c = q0 + warp_n * 32 + ni * 8 + tg * 2 + ci;
                atomicAdd(&g_colL [base + c], v);
                atomicAdd(&g_colLM[base + c], m);
            }
        }
}

// ---------------------------------------------------------------------------
// reduce: masked -log sums -> g_tot / g_cnt (32 blocks)
// ---------------------------------------------------------------------------
__global__ void reduce_kernel(const int* __restrict__ RM, const int* __restrict__ IM)
{
    __shared__ float s_t[256];
    __shared__ float s_c[256];
    int tid = threadIdx.x;
    float tot = 0.f, cnt = 0.f;
    for (int j = blockIdx.x * 256 + tid; j < NB * HW; j += 32 * 256) {
        {
            float l  = g_rowL[j] + 1e-6f;
            float v  = g_rowLM[j] / l;
            if (RM[j] > 0 && v != 0.0f) { tot -= logf(v); cnt += 1.f; }
        }
        {
            float l  = g_colL[j] + 1e-6f;
            float v  = g_colLM[j] / l;
            if (IM[j] > 0 && v != 0.0f) { tot -= logf(v); cnt += 1.f; }
        }
    }
    s_t[tid] = tot; s_c[tid] = cnt;
    __syncthreads();
    for (int s = 128; s > 0; s >>= 1) {
        if (tid < s) { s_t[tid] += s_t[tid + s]; s_c[tid] += s_c[tid + s]; }
        __syncthreads();
    }
    if (tid == 0) {
        atomicAdd(&g_tot, s_t[0]);
        atomicAdd(&g_cnt, s_c[0]);
    }
}

__global__ void div_kernel(float* __restrict__ out)
{
    out[0] = g_tot / g_cnt;
}

// ---------------------------------------------------------------------------
extern "C" void kernel_launch(void* const* d_in, const int* in_sizes, int n_in,
                              void* d_out, int out_size)
{
    const float* R  = (const float*)d_in[0];   // rgb_map  (N,C,H,W) fp32
    const float* I  = (const float*)d_in[1];   // ir_map   (N,C,H,W) fp32
    const int*   RM = (const int*)  d_in[2];   // rgb_mask (N,H,W)   int32
    const int*   IM = (const int*)  d_in[3];   // ir_mask  (N,H,W)   int32
    float* out = (float*)d_out;

    zero_kernel<<<(NB * HW + 255) / 256, 256>>>();
    prep_kernel<<<128, 256>>>(R, I);

    dim3 grid(HW / BN, HW / BM, NB);           // (8, 8, 8) = 512 CTAs
    tile_kernel<<<grid, 256>>>(RM, IM);

    reduce_kernel<<<32, 256>>>(RM, IM);
    div_kernel<<<1, 1>>>(out);
}